// round 7
// baseline (speedup 1.0000x reference)
#include <cuda_runtime.h>
#include <math.h>

// Problem constants (from reference: INPUT_SIZE=HIDDEN=2048, B=T=128)
#define HID   2048
#define BMAX  128
#define TSTEPS 128
#define MAXTOT (BMAX * TSTEPS)   // 16384 max packed tokens

// ---- scratch (device globals: no allocation allowed) ----
__device__ int   g_bsps[TSTEPS];
__device__ int   g_off[TSTEPS + 1];
__device__ float g_h[2][BMAX * HID];               // double-buffered hidden state
__device__ float g_z[(size_t)MAXTOT * HID];        // precomputed x @ W_ih^T + biases (128 MiB)

// ------------------------------------------------------------------
// Decode batch_size_per_step (int32 or int64, detected by byte pattern)
// and build prefix-sum offsets. All bsps values are >= 1, so int64
// little-endian data has zero odd words while int32 data does not.
// ------------------------------------------------------------------
__global__ void k_decode(const void* __restrict__ raw) {
    __shared__ int s_is64;
    int t = threadIdx.x;
    if (t == 0) {
        const int* p = (const int*)raw;
        int is64 = 1;
        for (int i = 0; i < 64; ++i) {
            if (p[2 * i + 1] != 0 || p[2 * i] <= 0) { is64 = 0; break; }
        }
        s_is64 = is64;
    }
    __syncthreads();
    int v;
    if (s_is64) v = (int)((const long long*)raw)[t];
    else        v = ((const int*)raw)[t];
    g_bsps[t] = v;
    __syncthreads();
    if (t == 0) {
        int s = 0;
        for (int i = 0; i < TSTEPS; ++i) { g_off[i] = s; s += g_bsps[i]; }
        g_off[TSTEPS] = s;
    }
}

__global__ void k_init_h(const float* __restrict__ hidden) {
    size_t i = (size_t)blockIdx.x * blockDim.x + threadIdx.x;
    g_h[0][i] = hidden[i];
}

// ------------------------------------------------------------------
// GEMM 1: Z[r, c] = sum_k x[r,k] * W_ih[c,k] + b_ih[c] + b_hh[c]
// 64x64 tile, 256 threads, 4x4 per-thread micro-tile, K-step 16.
// ------------------------------------------------------------------
__global__ void __launch_bounds__(256) k_gemm_x(
    const float* __restrict__ A,      // x [total, HID]
    const float* __restrict__ W,      // W_ih [HID, HID]
    const float* __restrict__ b_ih,
    const float* __restrict__ b_hh)
{
    int total = g_off[TSTEPS];
    int row0 = blockIdx.y * 64;
    if (row0 >= total) return;
    int col0 = blockIdx.x * 64;

    __shared__ float As[16][68];      // [k][m], padded
    __shared__ float Bs[16][68];      // [k][n], padded

    int tid = threadIdx.x;
    int lr = tid >> 2;                // 0..63 (row within tile for loads)
    int lk = (tid & 3) << 2;          // 0,4,8,12 (k within k-tile for loads)
    int tx = tid & 15;                // n micro-tile index
    int ty = tid >> 4;                // m micro-tile index

    float acc[4][4] = {};

    const float* Aptr = A + (size_t)(row0 + lr) * HID + lk;
    const float* Wptr = W + (size_t)(col0 + lr) * HID + lk;
    bool arow_ok = (row0 + lr) < total;

    for (int k0 = 0; k0 < HID; k0 += 16) {
        float4 av = arow_ok ? *(const float4*)(Aptr + k0)
                            : make_float4(0.f, 0.f, 0.f, 0.f);
        float4 bv = *(const float4*)(Wptr + k0);
        As[lk + 0][lr] = av.x; As[lk + 1][lr] = av.y;
        As[lk + 2][lr] = av.z; As[lk + 3][lr] = av.w;
        Bs[lk + 0][lr] = bv.x; Bs[lk + 1][lr] = bv.y;
        Bs[lk + 2][lr] = bv.z; Bs[lk + 3][lr] = bv.w;
        __syncthreads();
#pragma unroll
        for (int kk = 0; kk < 16; ++kk) {
            float a[4], b[4];
#pragma unroll
            for (int i = 0; i < 4; ++i) a[i] = As[kk][ty * 4 + i];
#pragma unroll
            for (int j = 0; j < 4; ++j) b[j] = Bs[kk][tx * 4 + j];
#pragma unroll
            for (int i = 0; i < 4; ++i)
#pragma unroll
                for (int j = 0; j < 4; ++j)
                    acc[i][j] += a[i] * b[j];
        }
        __syncthreads();
    }

#pragma unroll
    for (int i = 0; i < 4; ++i) {
        int r = row0 + ty * 4 + i;
        if (r >= total) continue;
#pragma unroll
        for (int j = 0; j < 4; ++j) {
            int c = col0 + tx * 4 + j;
            g_z[(size_t)r * HID + c] = acc[i][j] + b_ih[c] + b_hh[c];
        }
    }
}

// ------------------------------------------------------------------
// Recurrent step t:
//   hn[b,c] = tanh(Z[off+b, c] + sum_k hc[b,k] * W_hh[c,k])   for b < nb
//   hn[b,c] = hc[b,c]                                         for b >= nb
//   out[off+b, c] = hn[b,c]                                   for b < nb
// Double-buffered hidden state avoids read/write races across blocks.
// ------------------------------------------------------------------
__global__ void __launch_bounds__(256) k_step(
    const float* __restrict__ W,       // W_hh [HID, HID]
    float* __restrict__ out_packed,    // d_out + BMAX*HID
    int t)
{
    int nb  = g_bsps[t];
    int off = g_off[t];
    const float* hc = g_h[t & 1];
    float*       hn = g_h[(t + 1) & 1];

    int row0 = blockIdx.y * 64;
    int col0 = blockIdx.x * 64;
    int tid = threadIdx.x;

    if (row0 >= nb) {
        // whole tile inactive: carry hidden state
        for (int e = tid; e < 64 * 64; e += 256) {
            int r = row0 + (e >> 6);
            int c = col0 + (e & 63);
            hn[(size_t)r * HID + c] = hc[(size_t)r * HID + c];
        }
        return;
    }

    __shared__ float As[16][68];
    __shared__ float Bs[16][68];

    int lr = tid >> 2;
    int lk = (tid & 3) << 2;
    int tx = tid & 15;
    int ty = tid >> 4;

    float acc[4][4] = {};

    const float* Aptr = hc + (size_t)(row0 + lr) * HID + lk;
    const float* Wptr = W  + (size_t)(col0 + lr) * HID + lk;

    for (int k0 = 0; k0 < HID; k0 += 16) {
        float4 av = *(const float4*)(Aptr + k0);
        float4 bv = *(const float4*)(Wptr + k0);
        As[lk + 0][lr] = av.x; As[lk + 1][lr] = av.y;
        As[lk + 2][lr] = av.z; As[lk + 3][lr] = av.w;
        Bs[lk + 0][lr] = bv.x; Bs[lk + 1][lr] = bv.y;
        Bs[lk + 2][lr] = bv.z; Bs[lk + 3][lr] = bv.w;
        __syncthreads();
#pragma unroll
        for (int kk = 0; kk < 16; ++kk) {
            float a[4], b[4];
#pragma unroll
            for (int i = 0; i < 4; ++i) a[i] = As[kk][ty * 4 + i];
#pragma unroll
            for (int j = 0; j < 4; ++j) b[j] = Bs[kk][tx * 4 + j];
#pragma unroll
            for (int i = 0; i < 4; ++i)
#pragma unroll
                for (int j = 0; j < 4; ++j)
                    acc[i][j] += a[i] * b[j];
        }
        __syncthreads();
    }

#pragma unroll
    for (int i = 0; i < 4; ++i) {
        int r = row0 + ty * 4 + i;
#pragma unroll
        for (int j = 0; j < 4; ++j) {
            int c = col0 + tx * 4 + j;
            float v;
            if (r < nb) {
                v = tanhf(acc[i][j] + g_z[(size_t)(off + r) * HID + c]);
                out_packed[(size_t)(off + r) * HID + c] = v;
            } else {
                v = hc[(size_t)r * HID + c];
            }
            hn[(size_t)r * HID + c] = v;
        }
    }
}

// Final hidden state -> first BMAX*HID floats of d_out.
__global__ void k_final(float* __restrict__ out_h) {
    size_t i = (size_t)blockIdx.x * blockDim.x + threadIdx.x;
    out_h[i] = g_h[TSTEPS & 1][i];   // buffer 0 after 128 steps
}

extern "C" void kernel_launch(void* const* d_in, const int* in_sizes, int n_in,
                              void* d_out, int out_size)
{
    const float* x      = (const float*)d_in[0];
    const float* hidden = (const float*)d_in[1];
    const float* W_ih   = (const float*)d_in[2];
    const float* W_hh   = (const float*)d_in[3];
    const float* b_ih   = (const float*)d_in[4];
    const float* b_hh   = (const float*)d_in[5];
    const void*  bsps   = d_in[6];
    float* out = (float*)d_out;

    k_decode<<<1, 128>>>(bsps);
    k_init_h<<<(BMAX * HID) / 256, 256>>>(hidden);

    dim3 g1(HID / 64, MAXTOT / 64);
    k_gemm_x<<<g1, 256>>>(x, W_ih, b_ih, b_hh);

    dim3 gs(HID / 64, BMAX / 64);
    float* out_packed = out + (size_t)BMAX * HID;
    for (int t = 0; t < TSTEPS; ++t)
        k_step<<<gs, 256>>>(W_hh, out_packed, t);

    k_final<<<(BMAX * HID) / 256, 256>>>(out);
}

// round 8
// speedup vs baseline: 1.0033x; 1.0033x over previous
#include <cuda_runtime.h>
#include <math.h>

// Problem constants (from reference: INPUT_SIZE=HIDDEN=2048, B=T=128)
#define HID   2048
#define BMAX  128
#define TSTEPS 128
#define MAXTOT (BMAX * TSTEPS)   // 16384 max packed tokens

// ---- scratch (device globals: no allocation allowed) ----
__device__ int   g_bsps[TSTEPS];
__device__ int   g_off[TSTEPS + 1];
__device__ float g_h[2][BMAX * HID];               // double-buffered hidden state
__device__ float g_z[(size_t)MAXTOT * HID];        // precomputed x @ W_ih^T + biases (128 MiB)

// ------------------------------------------------------------------
// Decode batch_size_per_step (int32 or int64, detected by byte pattern)
// and build prefix-sum offsets. All bsps values are >= 1, so int64
// little-endian data has zero odd words while int32 data does not.
// ------------------------------------------------------------------
__global__ void k_decode(const void* __restrict__ raw) {
    __shared__ int s_is64;
    int t = threadIdx.x;
    if (t == 0) {
        const int* p = (const int*)raw;
        int is64 = 1;
        for (int i = 0; i < 64; ++i) {
            if (p[2 * i + 1] != 0 || p[2 * i] <= 0) { is64 = 0; break; }
        }
        s_is64 = is64;
    }
    __syncthreads();
    int v;
    if (s_is64) v = (int)((const long long*)raw)[t];
    else        v = ((const int*)raw)[t];
    g_bsps[t] = v;
    __syncthreads();
    if (t == 0) {
        int s = 0;
        for (int i = 0; i < TSTEPS; ++i) { g_off[i] = s; s += g_bsps[i]; }
        g_off[TSTEPS] = s;
    }
}

__global__ void k_init_h(const float* __restrict__ hidden) {
    size_t i = (size_t)blockIdx.x * blockDim.x + threadIdx.x;
    g_h[0][i] = hidden[i];
}

// ------------------------------------------------------------------
// GEMM 1: Z[r, c] = sum_k x[r,k] * W_ih[c,k] + b_ih[c] + b_hh[c]
// 64x64 tile, 256 threads, 4x4 per-thread micro-tile, K-step 16.
// ------------------------------------------------------------------
__global__ void __launch_bounds__(256) k_gemm_x(
    const float* __restrict__ A,      // x [total, HID]
    const float* __restrict__ W,      // W_ih [HID, HID]
    const float* __restrict__ b_ih,
    const float* __restrict__ b_hh)
{
    int total = g_off[TSTEPS];
    int row0 = blockIdx.y * 64;
    if (row0 >= total) return;
    int col0 = blockIdx.x * 64;

    __shared__ float As[16][68];      // [k][m], padded
    __shared__ float Bs[16][68];      // [k][n], padded

    int tid = threadIdx.x;
    int lr = tid >> 2;                // 0..63 (row within tile for loads)
    int lk = (tid & 3) << 2;          // 0,4,8,12 (k within k-tile for loads)
    int tx = tid & 15;                // n micro-tile index
    int ty = tid >> 4;                // m micro-tile index

    float acc[4][4] = {};

    const float* Aptr = A + (size_t)(row0 + lr) * HID + lk;
    const float* Wptr = W + (size_t)(col0 + lr) * HID + lk;
    bool arow_ok = (row0 + lr) < total;

    for (int k0 = 0; k0 < HID; k0 += 16) {
        float4 av = arow_ok ? *(const float4*)(Aptr + k0)
                            : make_float4(0.f, 0.f, 0.f, 0.f);
        float4 bv = *(const float4*)(Wptr + k0);
        As[lk + 0][lr] = av.x; As[lk + 1][lr] = av.y;
        As[lk + 2][lr] = av.z; As[lk + 3][lr] = av.w;
        Bs[lk + 0][lr] = bv.x; Bs[lk + 1][lr] = bv.y;
        Bs[lk + 2][lr] = bv.z; Bs[lk + 3][lr] = bv.w;
        __syncthreads();
#pragma unroll
        for (int kk = 0; kk < 16; ++kk) {
            float a[4], b[4];
#pragma unroll
            for (int i = 0; i < 4; ++i) a[i] = As[kk][ty * 4 + i];
#pragma unroll
            for (int j = 0; j < 4; ++j) b[j] = Bs[kk][tx * 4 + j];
#pragma unroll
            for (int i = 0; i < 4; ++i)
#pragma unroll
                for (int j = 0; j < 4; ++j)
                    acc[i][j] += a[i] * b[j];
        }
        __syncthreads();
    }

#pragma unroll
    for (int i = 0; i < 4; ++i) {
        int r = row0 + ty * 4 + i;
        if (r >= total) continue;
#pragma unroll
        for (int j = 0; j < 4; ++j) {
            int c = col0 + tx * 4 + j;
            g_z[(size_t)r * HID + c] = acc[i][j] + b_ih[c] + b_hh[c];
        }
    }
}

// ------------------------------------------------------------------
// Recurrent step t:
//   hn[b,c] = tanh(Z[off+b, c] + sum_k hc[b,k] * W_hh[c,k])   for b < nb
//   hn[b,c] = hc[b,c]                                         for b >= nb
//   out[off+b, c] = hn[b,c]                                   for b < nb
// Double-buffered hidden state avoids read/write races across blocks.
// ------------------------------------------------------------------
__global__ void __launch_bounds__(256) k_step(
    const float* __restrict__ W,       // W_hh [HID, HID]
    float* __restrict__ out_packed,    // d_out + BMAX*HID
    int t)
{
    int nb  = g_bsps[t];
    int off = g_off[t];
    const float* hc = g_h[t & 1];
    float*       hn = g_h[(t + 1) & 1];

    int row0 = blockIdx.y * 64;
    int col0 = blockIdx.x * 64;
    int tid = threadIdx.x;

    if (row0 >= nb) {
        // whole tile inactive: carry hidden state
        for (int e = tid; e < 64 * 64; e += 256) {
            int r = row0 + (e >> 6);
            int c = col0 + (e & 63);
            hn[(size_t)r * HID + c] = hc[(size_t)r * HID + c];
        }
        return;
    }

    __shared__ float As[16][68];
    __shared__ float Bs[16][68];

    int lr = tid >> 2;
    int lk = (tid & 3) << 2;
    int tx = tid & 15;
    int ty = tid >> 4;

    float acc[4][4] = {};

    const float* Aptr = hc + (size_t)(row0 + lr) * HID + lk;
    const float* Wptr = W  + (size_t)(col0 + lr) * HID + lk;

    for (int k0 = 0; k0 < HID; k0 += 16) {
        float4 av = *(const float4*)(Aptr + k0);
        float4 bv = *(const float4*)(Wptr + k0);
        As[lk + 0][lr] = av.x; As[lk + 1][lr] = av.y;
        As[lk + 2][lr] = av.z; As[lk + 3][lr] = av.w;
        Bs[lk + 0][lr] = bv.x; Bs[lk + 1][lr] = bv.y;
        Bs[lk + 2][lr] = bv.z; Bs[lk + 3][lr] = bv.w;
        __syncthreads();
#pragma unroll
        for (int kk = 0; kk < 16; ++kk) {
            float a[4], b[4];
#pragma unroll
            for (int i = 0; i < 4; ++i) a[i] = As[kk][ty * 4 + i];
#pragma unroll
            for (int j = 0; j < 4; ++j) b[j] = Bs[kk][tx * 4 + j];
#pragma unroll
            for (int i = 0; i < 4; ++i)
#pragma unroll
                for (int j = 0; j < 4; ++j)
                    acc[i][j] += a[i] * b[j];
        }
        __syncthreads();
    }

#pragma unroll
    for (int i = 0; i < 4; ++i) {
        int r = row0 + ty * 4 + i;
#pragma unroll
        for (int j = 0; j < 4; ++j) {
            int c = col0 + tx * 4 + j;
            float v;
            if (r < nb) {
                v = tanhf(acc[i][j] + g_z[(size_t)(off + r) * HID + c]);
                out_packed[(size_t)(off + r) * HID + c] = v;
            } else {
                v = hc[(size_t)r * HID + c];
            }
            hn[(size_t)r * HID + c] = v;
        }
    }
}

// Final hidden state -> first BMAX*HID floats of d_out.
__global__ void k_final(float* __restrict__ out_h) {
    size_t i = (size_t)blockIdx.x * blockDim.x + threadIdx.x;
    out_h[i] = g_h[TSTEPS & 1][i];   // buffer 0 after 128 steps
}

extern "C" void kernel_launch(void* const* d_in, const int* in_sizes, int n_in,
                              void* d_out, int out_size)
{
    const float* x      = (const float*)d_in[0];
    const float* hidden = (const float*)d_in[1];
    const float* W_ih   = (const float*)d_in[2];
    const float* W_hh   = (const float*)d_in[3];
    const float* b_ih   = (const float*)d_in[4];
    const float* b_hh   = (const float*)d_in[5];
    const void*  bsps   = d_in[6];
    float* out = (float*)d_out;

    k_decode<<<1, 128>>>(bsps);
    k_init_h<<<(BMAX * HID) / 256, 256>>>(hidden);

    dim3 g1(HID / 64, MAXTOT / 64);
    k_gemm_x<<<g1, 256>>>(x, W_ih, b_ih, b_hh);

    dim3 gs(HID / 64, BMAX / 64);
    float* out_packed = out + (size_t)BMAX * HID;
    for (int t = 0; t < TSTEPS; ++t)
        k_step<<<gs, 256>>>(W_hh, out_packed, t);

    k_final<<<(BMAX * HID) / 256, 256>>>(out);
}